// round 8
// baseline (speedup 1.0000x reference)
#include <cuda_runtime.h>
#include <cuda_fp16.h>

#define N_NODES 100000
#define N_EDGES 1600000
#define M_TOTAL (N_EDGES + N_NODES)
#define HD 128
#define NHEAD 4
#define NB ((N_NODES + 255) / 256)   // 391 scan blocks
#define GN 16                        // nodes per gemm group (100000 % 16 == 0)

// ---- scratch (device globals: the sanctioned no-alloc path) ----
__device__ __half g_h[N_NODES * HD];       // 25.6 MB transformed features (fp16)
__device__ float  g_asrc[N_NODES * NHEAD];
__device__ float  g_adst[N_NODES * NHEAD];
__device__ int    g_deg[N_NODES];
__device__ int    g_off[N_NODES + 1];      // CSR row offsets (by dst)
__device__ int    g_pos[N_NODES];          // scatter cursors
__device__ int    g_srcs[M_TOTAL];         // src ids grouped by dst
__device__ int    g_bsum[512];             // scan block sums

__device__ __forceinline__ float leaky(float e) { return e > 0.f ? e : 0.2f * e; }

// packed fp32x2 helpers (Blackwell: fma.rn.f32x2 — 2x fp32 FMA per instr)
__device__ __forceinline__ unsigned long long pack2(float x)
{
    unsigned long long r;
    asm("mov.b64 %0, {%1, %1};" : "=l"(r) : "f"(x));
    return r;
}
__device__ __forceinline__ void fma2(unsigned long long& d, unsigned long long a,
                                     unsigned long long b)
{
    asm("fma.rn.f32x2 %0, %1, %2, %0;" : "+l"(d) : "l"(a), "l"(b));
}

// ============================================================================
// K0: init degree = 1 (folds the self loop into the count)
// ============================================================================
__global__ void k_zero()
{
    int i = blockIdx.x * blockDim.x + threadIdx.x;
    if (i < N_NODES) g_deg[i] = 1;
}

// ============================================================================
// K1: h = x @ W, 16 nodes per group, FFMA2 (f32x2) inner loop.
// Thread t owns output channel t. W transposed in SMEM [c][k] (+4 pad) ->
// per-lane LDS.128. x staged NODE-TRANSPOSED xsT[k][j] ([128][20]) so node
// pairs read as ulonglong2 broadcasts feeding fma.rn.f32x2 directly.
// b-scalar packed once per k, reused by 8 FFMA2. Fused degree count + fused
// a_src/a_dst head reductions. h stored fp16 (logits from fp32 pre-rounding).
// ============================================================================
extern __shared__ float k1_smem[];
__global__ void k_gemm(const float* __restrict__ x, const float* __restrict__ W,
                       const float* __restrict__ att_src, const float* __restrict__ att_dst,
                       const int* __restrict__ ei)
{
    float* Wt  = k1_smem;              // [128][132] transposed, padded
    float* xsT = k1_smem + 128 * 132;  // [128][20]: 16 nodes + 4 pad
    const int t = threadIdx.x;         // output channel
    const int w = t >> 5, lane = t & 31;

    // fused degree count (edges only; self loops pre-folded in k_zero)
    for (int m = blockIdx.x * blockDim.x + t; m < N_EDGES; m += gridDim.x * blockDim.x)
        atomicAdd(&g_deg[ei[N_EDGES + m]], 1);

    for (int i = t; i < 128 * 128; i += 128) {
        int k = i >> 7, c = i & 127;
        Wt[c * 132 + k] = W[i];
    }
    const float atS = att_src[t];
    const float atD = att_dst[t];
    const float4* wv = (const float4*)(Wt + t * 132);  // 16B aligned (132*4)

    for (int g = blockIdx.x; g < N_NODES / GN; g += gridDim.x) {
        const int n0 = g * GN;
        __syncthreads();   // protect xsT from previous iteration (and Wt staging)
#pragma unroll
        for (int j = 0; j < GN; j++)
            xsT[t * 20 + j] = x[(n0 + j) * HD + t];
        __syncthreads();

        unsigned long long acc[8];  // 8 node-pairs, channel t
#pragma unroll
        for (int p = 0; p < 8; p++) acc[p] = 0ull;  // (0.f,0.f)

#pragma unroll 4
        for (int k4 = 0; k4 < 32; k4++) {
            float4 b4 = wv[k4];
#pragma unroll
            for (int kk = 0; kk < 4; kk++) {
                const int k = k4 * 4 + kk;
                float b = (kk == 0) ? b4.x : (kk == 1) ? b4.y : (kk == 2) ? b4.z : b4.w;
                unsigned long long bb = pack2(b);
                const ulonglong2* ap = (const ulonglong2*)(xsT + k * 20);  // bcast LDS.128
#pragma unroll
                for (int p2 = 0; p2 < 4; p2++) {
                    ulonglong2 a2 = ap[p2];
                    fma2(acc[p2 * 2 + 0], a2.x, bb);
                    fma2(acc[p2 * 2 + 1], a2.y, bb);
                }
            }
        }

#pragma unroll
        for (int p = 0; p < 8; p++) {
            float2 av = *(float2*)&acc[p];  // .x = node 2p, .y = node 2p+1
            const int j0 = n0 + 2 * p, j1 = j0 + 1;
            g_h[(long long)j0 * HD + t] = __float2half(av.x);
            g_h[(long long)j1 * HD + t] = __float2half(av.y);

            float s0 = av.x * atS, d0 = av.x * atD;
            float s1 = av.y * atS, d1 = av.y * atD;
#pragma unroll
            for (int o = 16; o; o >>= 1) {
                s0 += __shfl_xor_sync(0xffffffffu, s0, o);
                d0 += __shfl_xor_sync(0xffffffffu, d0, o);
                s1 += __shfl_xor_sync(0xffffffffu, s1, o);
                d1 += __shfl_xor_sync(0xffffffffu, d1, o);
            }
            if (lane == 0) {
                g_asrc[j0 * NHEAD + w] = s0;
                g_adst[j0 * NHEAD + w] = d0;
                g_asrc[j1 * NHEAD + w] = s1;
                g_adst[j1 * NHEAD + w] = d1;
            }
        }
    }
}

// ============================================================================
// CSR build: block scan -> (block-prefix + apply) -> scatter
// ============================================================================
__global__ void k_scanA()
{
    __shared__ int s[256];
    int t = threadIdx.x;
    int i = blockIdx.x * 256 + t;
    int v = (i < N_NODES) ? g_deg[i] : 0;
    s[t] = v;
    __syncthreads();
#pragma unroll
    for (int off = 1; off < 256; off <<= 1) {
        int u = (t >= off) ? s[t - off] : 0;
        __syncthreads();
        s[t] += u;
        __syncthreads();
    }
    if (i < N_NODES) g_off[i] = s[t] - v;       // exclusive within block
    if (t == 255) g_bsum[blockIdx.x] = s[255];  // block total
}

__global__ void k_scanC()  // fuses global block-prefix with the apply step
{
    __shared__ int pref;
    int t = threadIdx.x;
    if (t < 32) {
        int s = 0;
        for (int i = t; i < blockIdx.x; i += 32) s += g_bsum[i];
#pragma unroll
        for (int o = 16; o; o >>= 1) s += __shfl_xor_sync(0xffffffffu, s, o);
        if (t == 0) pref = s;
    }
    __syncthreads();
    int i = blockIdx.x * 256 + t;
    if (i < N_NODES) {
        int o = g_off[i] + pref;
        g_off[i] = o;
        g_pos[i] = o;
    }
    if (i == 0) g_off[N_NODES] = M_TOTAL;
}

__global__ void k_scatter(const int* __restrict__ ei)
{
    int m = blockIdx.x * blockDim.x + threadIdx.x;
    if (m >= M_TOTAL) return;
    int src, dst;
    if (m < N_EDGES) { src = ei[m]; dst = ei[N_EDGES + m]; }
    else             { src = dst = m - N_EDGES; }
    int p = atomicAdd(&g_pos[dst], 1);
    g_srcs[p] = src;
}

// ============================================================================
// K_agg: one warp per dst node, DEPTH-4 software pipeline (MLP ~8/warp).
// Lane l owns channels [4l,4l+4) -> head l>>3. alpha = exp(leaky(.)) without
// max-shift (softmax shift-invariant, |logit| small). fp16 h gather (8B/lane,
// 256B/warp coalesced) accumulated in fp32; normalize+bias+ELU, single store.
// ============================================================================
__global__ void k_agg(const float* __restrict__ bias, float* __restrict__ out)
{
    int n = (blockIdx.x * blockDim.x + threadIdx.x) >> 5;
    int lane = threadIdx.x & 31;
    if (n >= N_NODES) return;
    const int h = lane >> 3;

    const int row = g_off[n];
    const int end = g_off[n + 1];
    const float adh = g_adst[n * NHEAD + h];

    float4 acc = make_float4(0.f, 0.f, 0.f, 0.f);
    float denom = 0.f;

    for (int base = row; base < end; base += 32) {
        const int cnt = min(32, end - base);
        int s_reg = (lane < cnt) ? g_srcs[base + lane] : 0;

        float as[4];
        unsigned long long hu[4];
#define AGG_ISSUE(q, jj)                                                          \
        do { if ((jj) < cnt) {                                                    \
            int s_ = __shfl_sync(0xffffffffu, s_reg, (jj));                       \
            as[q] = __ldg(&g_asrc[s_ * NHEAD + h]);                               \
            hu[q] = *(const unsigned long long*)(g_h + (long long)s_ * HD + lane * 4); \
        } } while (0)

        AGG_ISSUE(0, 0); AGG_ISSUE(1, 1); AGG_ISSUE(2, 2); AGG_ISSUE(3, 3);

#pragma unroll 4
        for (int j = 0; j < cnt; j++) {
            const int q = j & 3;
            float ex = __expf(leaky(as[q] + adh));
            unsigned long long hc = hu[q];
            AGG_ISSUE(q, j + 4);   // refill slot before the long-latency use gap
            __half2 p0 = *((__half2*)&hc);
            __half2 p1 = *(((__half2*)&hc) + 1);
            float2 f0 = __half22float2(p0);
            float2 f1 = __half22float2(p1);
            denom += ex;
            acc.x = fmaf(ex, f0.x, acc.x);
            acc.y = fmaf(ex, f0.y, acc.y);
            acc.z = fmaf(ex, f1.x, acc.z);
            acc.w = fmaf(ex, f1.y, acc.w);
        }
#undef AGG_ISSUE
    }

    const float inv = 1.f / (denom + 1e-16f);
    float4 b4 = ((const float4*)bias)[lane];
    float4 o;
    o.x = acc.x * inv + b4.x;
    o.y = acc.y * inv + b4.y;
    o.z = acc.z * inv + b4.z;
    o.w = acc.w * inv + b4.w;
    o.x = o.x > 0.f ? o.x : expm1f(o.x);
    o.y = o.y > 0.f ? o.y : expm1f(o.y);
    o.z = o.z > 0.f ? o.z : expm1f(o.z);
    o.w = o.w > 0.f ? o.w : expm1f(o.w);
    *((float4*)out + (long long)n * 32 + lane) = o;
}

// ============================================================================
extern "C" void kernel_launch(void* const* d_in, const int* in_sizes, int n_in,
                              void* d_out, int out_size)
{
    const float* x    = (const float*)d_in[0];
    const int*   ei   = (const int*)d_in[1];     // int32 (JAX x64 disabled)
    const float* W    = (const float*)d_in[2];
    const float* aS   = (const float*)d_in[3];
    const float* aD   = (const float*)d_in[4];
    const float* bias = (const float*)d_in[5];
    float*       out  = (float*)d_out;

    const int smem = (128 * 132 + 128 * 20) * (int)sizeof(float);  // 77824 B
    cudaFuncSetAttribute(k_gemm, cudaFuncAttributeMaxDynamicSharedMemorySize, smem);

    k_zero<<<NB, 256>>>();
    k_gemm<<<444, 128, smem>>>(x, W, aS, aD, ei);
    k_scanA<<<NB, 256>>>();
    k_scanC<<<NB, 256>>>();
    k_scatter<<<(M_TOTAL + 255) / 256, 256>>>(ei);
    k_agg<<<(N_NODES * 32 + 255) / 256, 256>>>(bias, out);
}

// round 9
// speedup vs baseline: 1.1569x; 1.1569x over previous
#include <cuda_runtime.h>
#include <cuda_fp16.h>

#define N_NODES 100000
#define N_EDGES 1600000
#define M_TOTAL (N_EDGES + N_NODES)
#define HD 128
#define NHEAD 4
#define NB ((N_NODES + 255) / 256)   // 391 scan blocks

// ---- scratch (device globals: the sanctioned no-alloc path) ----
__device__ __half g_h[N_NODES * HD];       // 25.6 MB transformed features (fp16)
__device__ float  g_asrc[N_NODES * NHEAD];
__device__ float  g_adst[N_NODES * NHEAD];
__device__ int    g_deg[N_NODES];
__device__ int    g_off[N_NODES + 1];      // CSR row offsets (by dst)
__device__ int    g_pos[N_NODES];          // scatter cursors
__device__ int    g_srcs[M_TOTAL];         // src ids grouped by dst
__device__ int    g_bsum[512];             // scan block sums

__device__ __forceinline__ float leaky(float e) { return e > 0.f ? e : 0.2f * e; }

// ============================================================================
// K0: init degree = 1 (folds the self loop into the count)
// ============================================================================
__global__ void k_zero()
{
    int i = blockIdx.x * blockDim.x + threadIdx.x;
    if (i < N_NODES) g_deg[i] = 1;
}

// ============================================================================
// K1 (R5-proven form): h = x @ W with 8-node register blocking + fused degree
// count. W transposed in SMEM (+4 pad), thread reads its W column once per 8
// nodes; x rows are warp-broadcast reads. Fused a_src/a_dst head reductions.
// h stored fp16 (logits computed from fp32 accumulators BEFORE rounding).
// ============================================================================
extern __shared__ float k1_smem[];
__global__ void k_gemm(const float* __restrict__ x, const float* __restrict__ W,
                       const float* __restrict__ att_src, const float* __restrict__ att_dst,
                       const int* __restrict__ ei)
{
    float* Wt = k1_smem;              // [128][132] transposed, padded
    float* xs = k1_smem + 128 * 132;  // [8][128]
    const int t = threadIdx.x;        // output channel
    const int w = t >> 5, lane = t & 31;

    // fused degree count (edges only; self loops pre-folded in k_zero)
    for (int m = blockIdx.x * blockDim.x + t; m < N_EDGES; m += gridDim.x * blockDim.x)
        atomicAdd(&g_deg[ei[N_EDGES + m]], 1);

    for (int i = t; i < 128 * 128; i += 128) {
        int k = i >> 7, c = i & 127;
        Wt[c * 132 + k] = W[i];
    }
    const float atS = att_src[t];
    const float atD = att_dst[t];
    const float4* wv = (const float4*)(Wt + t * 132);  // 16B aligned (132*4)

    for (int g = blockIdx.x; g < N_NODES / 8; g += gridDim.x) {
        const int n0 = g * 8;
        __syncthreads();   // protect xs from previous iteration (and Wt staging)
#pragma unroll
        for (int j = 0; j < 8; j++)
            xs[j * 128 + t] = x[(n0 + j) * HD + t];
        __syncthreads();

        float acc[8] = {0.f, 0.f, 0.f, 0.f, 0.f, 0.f, 0.f, 0.f};
#pragma unroll 8
        for (int k = 0; k < 32; k++) {
            float4 b = wv[k];
#pragma unroll
            for (int j = 0; j < 8; j++) {
                float4 a = ((const float4*)(xs + j * 128))[k];  // warp broadcast
                acc[j] = fmaf(a.x, b.x, fmaf(a.y, b.y, fmaf(a.z, b.z, fmaf(a.w, b.w, acc[j]))));
            }
        }
#pragma unroll
        for (int j = 0; j < 8; j++)
            g_h[(n0 + j) * HD + t] = __float2half(acc[j]);

#pragma unroll
        for (int j = 0; j < 8; j++) {
            float s = acc[j] * atS;
            float d = acc[j] * atD;
#pragma unroll
            for (int o = 16; o; o >>= 1) {
                s += __shfl_xor_sync(0xffffffffu, s, o);
                d += __shfl_xor_sync(0xffffffffu, d, o);
            }
            if (lane == 0) {
                g_asrc[(n0 + j) * NHEAD + w] = s;
                g_adst[(n0 + j) * NHEAD + w] = d;
            }
        }
    }
}

// ============================================================================
// CSR build: block scan -> (block-prefix + apply) -> scatter
// ============================================================================
__global__ void k_scanA()
{
    __shared__ int s[256];
    int t = threadIdx.x;
    int i = blockIdx.x * 256 + t;
    int v = (i < N_NODES) ? g_deg[i] : 0;
    s[t] = v;
    __syncthreads();
#pragma unroll
    for (int off = 1; off < 256; off <<= 1) {
        int u = (t >= off) ? s[t - off] : 0;
        __syncthreads();
        s[t] += u;
        __syncthreads();
    }
    if (i < N_NODES) g_off[i] = s[t] - v;       // exclusive within block
    if (t == 255) g_bsum[blockIdx.x] = s[255];  // block total
}

__global__ void k_scanC()  // fuses global block-prefix with the apply step
{
    __shared__ int pref;
    int t = threadIdx.x;
    if (t < 32) {
        int s = 0;
        for (int i = t; i < blockIdx.x; i += 32) s += g_bsum[i];
#pragma unroll
        for (int o = 16; o; o >>= 1) s += __shfl_xor_sync(0xffffffffu, s, o);
        if (t == 0) pref = s;
    }
    __syncthreads();
    int i = blockIdx.x * 256 + t;
    if (i < N_NODES) {
        int o = g_off[i] + pref;
        g_off[i] = o;
        g_pos[i] = o;
    }
    if (i == 0) g_off[N_NODES] = M_TOTAL;
}

__global__ void k_scatter(const int* __restrict__ ei)
{
    int m = blockIdx.x * blockDim.x + threadIdx.x;
    if (m >= M_TOTAL) return;
    int src, dst;
    if (m < N_EDGES) { src = ei[m]; dst = ei[N_EDGES + m]; }
    else             { src = dst = m - N_EDGES; }
    int p = atomicAdd(&g_pos[dst], 1);
    g_srcs[p] = src;
}

// ============================================================================
// K_agg: one warp per dst node, DEPTH-4 software pipeline (MLP ~8/warp).
// Lane l owns channels [4l,4l+4) -> head l>>3. alpha = exp(leaky(.)) without
// max-shift (softmax shift-invariant, |logit| small). fp16 h gather (8B/lane,
// 256B/warp coalesced) accumulated in fp32; normalize+bias+ELU, single store.
// ============================================================================
__global__ void k_agg(const float* __restrict__ bias, float* __restrict__ out)
{
    int n = (blockIdx.x * blockDim.x + threadIdx.x) >> 5;
    int lane = threadIdx.x & 31;
    if (n >= N_NODES) return;
    const int h = lane >> 3;

    const int row = g_off[n];
    const int end = g_off[n + 1];
    const float adh = g_adst[n * NHEAD + h];

    float4 acc = make_float4(0.f, 0.f, 0.f, 0.f);
    float denom = 0.f;

    for (int base = row; base < end; base += 32) {
        const int cnt = min(32, end - base);
        int s_reg = (lane < cnt) ? g_srcs[base + lane] : 0;

        float as[4];
        unsigned long long hu[4];
#define AGG_ISSUE(q, jj)                                                          \
        do { if ((jj) < cnt) {                                                    \
            int s_ = __shfl_sync(0xffffffffu, s_reg, (jj));                       \
            as[q] = __ldg(&g_asrc[s_ * NHEAD + h]);                               \
            hu[q] = *(const unsigned long long*)(g_h + (long long)s_ * HD + lane * 4); \
        } } while (0)

        AGG_ISSUE(0, 0); AGG_ISSUE(1, 1); AGG_ISSUE(2, 2); AGG_ISSUE(3, 3);

#pragma unroll 4
        for (int j = 0; j < cnt; j++) {
            const int q = j & 3;
            float ex = __expf(leaky(as[q] + adh));
            unsigned long long hc = hu[q];
            AGG_ISSUE(q, j + 4);   // refill slot before the long-latency use gap
            __half2 p0 = *((__half2*)&hc);
            __half2 p1 = *(((__half2*)&hc) + 1);
            float2 f0 = __half22float2(p0);
            float2 f1 = __half22float2(p1);
            denom += ex;
            acc.x = fmaf(ex, f0.x, acc.x);
            acc.y = fmaf(ex, f0.y, acc.y);
            acc.z = fmaf(ex, f1.x, acc.z);
            acc.w = fmaf(ex, f1.y, acc.w);
        }
#undef AGG_ISSUE
    }

    const float inv = 1.f / (denom + 1e-16f);
    float4 b4 = ((const float4*)bias)[lane];
    float4 o;
    o.x = acc.x * inv + b4.x;
    o.y = acc.y * inv + b4.y;
    o.z = acc.z * inv + b4.z;
    o.w = acc.w * inv + b4.w;
    o.x = o.x > 0.f ? o.x : expm1f(o.x);
    o.y = o.y > 0.f ? o.y : expm1f(o.y);
    o.z = o.z > 0.f ? o.z : expm1f(o.z);
    o.w = o.w > 0.f ? o.w : expm1f(o.w);
    *((float4*)out + (long long)n * 32 + lane) = o;
}

// ============================================================================
extern "C" void kernel_launch(void* const* d_in, const int* in_sizes, int n_in,
                              void* d_out, int out_size)
{
    const float* x    = (const float*)d_in[0];
    const int*   ei   = (const int*)d_in[1];     // int32 (JAX x64 disabled)
    const float* W    = (const float*)d_in[2];
    const float* aS   = (const float*)d_in[3];
    const float* aD   = (const float*)d_in[4];
    const float* bias = (const float*)d_in[5];
    float*       out  = (float*)d_out;

    const int smem = (128 * 132 + 8 * 128) * (int)sizeof(float);  // 71680 B
    cudaFuncSetAttribute(k_gemm, cudaFuncAttributeMaxDynamicSharedMemorySize, smem);

    k_zero<<<NB, 256>>>();
    k_gemm<<<444, 128, smem>>>(x, W, aS, aD, ei);
    k_scanA<<<NB, 256>>>();
    k_scanC<<<NB, 256>>>();
    k_scatter<<<(M_TOTAL + 255) / 256, 256>>>(ei);
    k_agg<<<(N_NODES * 32 + 255) / 256, 256>>>(bias, out);
}

// round 10
// speedup vs baseline: 1.7118x; 1.4797x over previous
#include <cuda_runtime.h>
#include <cuda_fp16.h>

#define N_NODES 100000
#define N_EDGES 1600000
#define M_TOTAL (N_EDGES + N_NODES)
#define HD 128
#define NHEAD 4
#define NB ((N_NODES + 255) / 256)   // 391 scan blocks

// ---- scratch (device globals: the sanctioned no-alloc path) ----
__device__ __half g_h[N_NODES * HD];       // 25.6 MB transformed features (fp16)
__device__ float  g_asrc[N_NODES * NHEAD];
__device__ float  g_adst[N_NODES * NHEAD];
__device__ float  g_u[HD * 8];             // u[k][j]: j<4 -> src head j, j>=4 -> dst head j-4
__device__ int    g_deg[N_NODES];
__device__ int    g_off[N_NODES + 1];      // CSR row offsets (by dst)
__device__ int    g_pos[N_NODES];          // scatter cursors
__device__ int    g_srcs[M_TOTAL];         // src ids grouped by dst
__device__ int    g_bsum[512];             // scan block sums

__device__ __forceinline__ float leaky(float e) { return e > 0.f ? e : 0.2f * e; }

__device__ __forceinline__ unsigned tf32(float f)
{
    unsigned u;
    asm("cvt.rna.tf32.f32 %0, %1;" : "=r"(u) : "f"(f));
    return u;
}

// ============================================================================
// K0: init degree = 1 (folds the self loop into the count)
// ============================================================================
__global__ void k_zero()
{
    int i = blockIdx.x * blockDim.x + threadIdx.x;
    if (i < N_NODES) g_deg[i] = 1;
}

// ============================================================================
// K_u: u = W @ att  (exact fp32; 1024 length-32 dots). u[k][j].
// ============================================================================
__global__ void k_u(const float* __restrict__ W, const float* __restrict__ att_src,
                    const float* __restrict__ att_dst)
{
    int t = threadIdx.x;
    for (int e = t; e < HD * 8; e += 256) {
        int k = e >> 3, j = e & 7;
        int head = j & 3;
        const float* att = (j < 4) ? att_src : att_dst;
        float s = 0.f;
#pragma unroll
        for (int d = 0; d < 32; d++)
            s = fmaf(W[k * HD + head * 32 + d], att[head * 32 + d], s);
        g_u[k * 8 + j] = s;
    }
}

// ============================================================================
// K_logits: a = x @ u  (exact fp32 logits; removes exp-path from tf32 error).
// thread -> (node, j). Consecutive 8 threads share a row (coalesced/broadcast).
// ============================================================================
__global__ void k_logits(const float* __restrict__ x)
{
    int gid = blockIdx.x * blockDim.x + threadIdx.x;
    if (gid >= N_NODES * 8) return;
    int n = gid >> 3, j = gid & 7;
    const float4* xr = (const float4*)(x + (long long)n * HD);
    float s = 0.f;
#pragma unroll 8
    for (int k = 0; k < 32; k++) {
        float4 xv = __ldg(&xr[k]);
        s = fmaf(xv.x, __ldg(&g_u[(k * 4 + 0) * 8 + j]),
            fmaf(xv.y, __ldg(&g_u[(k * 4 + 1) * 8 + j]),
            fmaf(xv.z, __ldg(&g_u[(k * 4 + 2) * 8 + j]),
            fmaf(xv.w, __ldg(&g_u[(k * 4 + 3) * 8 + j]), s))));
    }
    if (j < 4) g_asrc[n * NHEAD + j] = s;
    else       g_adst[n * NHEAD + (j - 4)] = s;
}

// ============================================================================
// K_gemm_tc: h = x @ W via mma.sync.m16n8k8.tf32. 256 threads = 8 warps; each
// warp owns 16 output rows x all 128 cols (16 n8-tiles). W staged in smem
// stride 136 (conflict-free B-frag LDS); A-frags loaded direct from global
// with cvt.rna. h stored fp16. Fused edge degree count.
// ============================================================================
extern __shared__ float tc_smem[];  // Ws[128][136]
__global__ void __launch_bounds__(256) k_gemm_tc(const float* __restrict__ x,
                                                 const float* __restrict__ W,
                                                 const int* __restrict__ ei)
{
    float* Ws = tc_smem;
    const int t = threadIdx.x, warp = t >> 5, lane = t & 31;

    // fused degree count (edges only; self loops pre-folded in k_zero)
    for (int m = blockIdx.x * blockDim.x + t; m < N_EDGES; m += gridDim.x * blockDim.x)
        atomicAdd(&g_deg[ei[N_EDGES + m]], 1);

    // stage W as tf32 bit patterns
    for (int i = t; i < HD * HD; i += 256) {
        int k = i >> 7, c = i & 127;
        Ws[k * 136 + c] = __uint_as_float(tf32(W[i]));
    }
    __syncthreads();

    const int row0 = blockIdx.x * 128 + warp * 16;
    const int ra = row0 + (lane >> 2);      // A rows: ra, ra+8
    const int qa = lane & 3;                // A col within k-step

    float acc[16][4];
#pragma unroll
    for (int nt = 0; nt < 16; nt++)
#pragma unroll
        for (int q = 0; q < 4; q++) acc[nt][q] = 0.f;

    for (int k0 = 0; k0 < HD; k0 += 8) {
        unsigned a0 = 0, a1 = 0, a2 = 0, a3 = 0;
        if (ra < N_NODES) {
            a0 = tf32(x[(long long)ra * HD + k0 + qa]);
            a2 = tf32(x[(long long)ra * HD + k0 + qa + 4]);
        }
        if (ra + 8 < N_NODES) {
            a1 = tf32(x[(long long)(ra + 8) * HD + k0 + qa]);
            a3 = tf32(x[(long long)(ra + 8) * HD + k0 + qa + 4]);
        }
        const int kb = k0 + (lane & 3);
        const int cb = lane >> 2;
#pragma unroll
        for (int nt = 0; nt < 16; nt++) {
            unsigned b0 = __float_as_uint(Ws[kb * 136 + nt * 8 + cb]);
            unsigned b1 = __float_as_uint(Ws[(kb + 4) * 136 + nt * 8 + cb]);
            asm volatile(
                "mma.sync.aligned.m16n8k8.row.col.f32.tf32.tf32.f32 "
                "{%0,%1,%2,%3}, {%4,%5,%6,%7}, {%8,%9}, {%0,%1,%2,%3};"
                : "+f"(acc[nt][0]), "+f"(acc[nt][1]), "+f"(acc[nt][2]), "+f"(acc[nt][3])
                : "r"(a0), "r"(a1), "r"(a2), "r"(a3), "r"(b0), "r"(b1));
        }
    }

    // store h fp16: c0,c1 -> (ra, col..col+1); c2,c3 -> (ra+8, same cols)
#pragma unroll
    for (int nt = 0; nt < 16; nt++) {
        const int col = nt * 8 + 2 * (lane & 3);
        if (ra < N_NODES)
            *(__half2*)(g_h + (long long)ra * HD + col) =
                __floats2half2_rn(acc[nt][0], acc[nt][1]);
        if (ra + 8 < N_NODES)
            *(__half2*)(g_h + (long long)(ra + 8) * HD + col) =
                __floats2half2_rn(acc[nt][2], acc[nt][3]);
    }
}

// ============================================================================
// CSR build: block scan -> (block-prefix + apply) -> scatter
// ============================================================================
__global__ void k_scanA()
{
    __shared__ int s[256];
    int t = threadIdx.x;
    int i = blockIdx.x * 256 + t;
    int v = (i < N_NODES) ? g_deg[i] : 0;
    s[t] = v;
    __syncthreads();
#pragma unroll
    for (int off = 1; off < 256; off <<= 1) {
        int u = (t >= off) ? s[t - off] : 0;
        __syncthreads();
        s[t] += u;
        __syncthreads();
    }
    if (i < N_NODES) g_off[i] = s[t] - v;       // exclusive within block
    if (t == 255) g_bsum[blockIdx.x] = s[255];  // block total
}

__global__ void k_scanC()  // fuses global block-prefix with the apply step
{
    __shared__ int pref;
    int t = threadIdx.x;
    if (t < 32) {
        int s = 0;
        for (int i = t; i < blockIdx.x; i += 32) s += g_bsum[i];
#pragma unroll
        for (int o = 16; o; o >>= 1) s += __shfl_xor_sync(0xffffffffu, s, o);
        if (t == 0) pref = s;
    }
    __syncthreads();
    int i = blockIdx.x * 256 + t;
    if (i < N_NODES) {
        int o = g_off[i] + pref;
        g_off[i] = o;
        g_pos[i] = o;
    }
    if (i == 0) g_off[N_NODES] = M_TOTAL;
}

__global__ void k_scatter(const int* __restrict__ ei)
{
    int m = blockIdx.x * blockDim.x + threadIdx.x;
    if (m >= M_TOTAL) return;
    int src, dst;
    if (m < N_EDGES) { src = ei[m]; dst = ei[N_EDGES + m]; }
    else             { src = dst = m - N_EDGES; }
    int p = atomicAdd(&g_pos[dst], 1);
    g_srcs[p] = src;
}

// ============================================================================
// K_agg (R6-proven depth-1 form): one warp per dst node. Lane l owns channels
// [4l,4l+4) -> head l>>3. alpha = exp(leaky(.)) without max-shift (softmax is
// shift-invariant; |logit| small). fp16 h gather (8B/lane, 256B/warp
// coalesced) accumulated in fp32; normalize+bias+ELU, single float4 store.
// ============================================================================
__global__ void k_agg(const float* __restrict__ bias, float* __restrict__ out)
{
    int n = (blockIdx.x * blockDim.x + threadIdx.x) >> 5;
    int lane = threadIdx.x & 31;
    if (n >= N_NODES) return;
    const int h = lane >> 3;

    const int row = g_off[n];
    const int end = g_off[n + 1];
    const float adh = g_adst[n * NHEAD + h];

    float4 acc = make_float4(0.f, 0.f, 0.f, 0.f);
    float denom = 0.f;

    for (int base = row; base < end; base += 32) {
        const int cnt = min(32, end - base);
        int s_reg = (lane < cnt) ? g_srcs[base + lane] : 0;

        // depth-1 pipeline: prefetch edge j+1 while computing edge j
        int src_c = __shfl_sync(0xffffffffu, s_reg, 0);
        float as_c = g_asrc[src_c * NHEAD + h];
        unsigned long long hu_c =
            *(const unsigned long long*)(g_h + (long long)src_c * HD + lane * 4);

        for (int j = 0; j < cnt; j++) {
            float as_n = 0.f;
            unsigned long long hu_n = 0ull;
            if (j + 1 < cnt) {
                int src_n = __shfl_sync(0xffffffffu, s_reg, j + 1);
                as_n = g_asrc[src_n * NHEAD + h];
                hu_n = *(const unsigned long long*)(g_h + (long long)src_n * HD + lane * 4);
            }
            float ex = __expf(leaky(as_c + adh));
            denom += ex;
            __half2 p0 = *((__half2*)&hu_c);
            __half2 p1 = *(((__half2*)&hu_c) + 1);
            float2 f0 = __half22float2(p0);
            float2 f1 = __half22float2(p1);
            acc.x = fmaf(ex, f0.x, acc.x);
            acc.y = fmaf(ex, f0.y, acc.y);
            acc.z = fmaf(ex, f1.x, acc.z);
            acc.w = fmaf(ex, f1.y, acc.w);
            as_c = as_n;
            hu_c = hu_n;
        }
    }

    const float inv = 1.f / (denom + 1e-16f);
    float4 b4 = ((const float4*)bias)[lane];
    float4 o;
    o.x = acc.x * inv + b4.x;
    o.y = acc.y * inv + b4.y;
    o.z = acc.z * inv + b4.z;
    o.w = acc.w * inv + b4.w;
    o.x = o.x > 0.f ? o.x : expm1f(o.x);
    o.y = o.y > 0.f ? o.y : expm1f(o.y);
    o.z = o.z > 0.f ? o.z : expm1f(o.z);
    o.w = o.w > 0.f ? o.w : expm1f(o.w);
    *((float4*)out + (long long)n * 32 + lane) = o;
}

// ============================================================================
extern "C" void kernel_launch(void* const* d_in, const int* in_sizes, int n_in,
                              void* d_out, int out_size)
{
    const float* x    = (const float*)d_in[0];
    const int*   ei   = (const int*)d_in[1];     // int32 (JAX x64 disabled)
    const float* W    = (const float*)d_in[2];
    const float* aS   = (const float*)d_in[3];
    const float* aD   = (const float*)d_in[4];
    const float* bias = (const float*)d_in[5];
    float*       out  = (float*)d_out;

    const int tc_smem_bytes = 128 * 136 * (int)sizeof(float);  // 69632 B
    cudaFuncSetAttribute(k_gemm_tc, cudaFuncAttributeMaxDynamicSharedMemorySize,
                         tc_smem_bytes);

    k_zero<<<NB, 256>>>();                                     // idx 0
    k_u<<<1, 256>>>(W, aS, aD);                                // idx 1
    k_logits<<<(N_NODES * 8 + 255) / 256, 256>>>(x);           // idx 2
    k_gemm_tc<<<(N_NODES + 127) / 128, 256, tc_smem_bytes>>>(x, W, ei);  // idx 3 (profiled)
    k_scanA<<<NB, 256>>>();                                    // idx 4
    k_scanC<<<NB, 256>>>();                                    // idx 5
    k_scatter<<<(M_TOTAL + 255) / 256, 256>>>(ei);             // idx 6
    k_agg<<<(N_NODES * 32 + 255) / 256, 256>>>(bias, out);     // idx 7
}

// round 11
// speedup vs baseline: 1.7787x; 1.0391x over previous
#include <cuda_runtime.h>
#include <cuda_fp16.h>

#define N_NODES 100000
#define N_EDGES 1600000
#define M_TOTAL (N_EDGES + N_NODES)
#define HD 128
#define NHEAD 4
#define NB ((N_NODES + 255) / 256)   // 391 scan blocks
#define NSTRIP ((N_NODES + 127) / 128)  // 782 gemm strips

// ---- scratch (device globals: the sanctioned no-alloc path) ----
__device__ __half g_h[N_NODES * HD];       // 25.6 MB transformed features (fp16)
__device__ float  g_asrc[N_NODES * NHEAD];
__device__ float  g_adst[N_NODES * NHEAD];
__device__ float  g_u[HD * 8];             // u[k][j]: j<4 -> src head j, j>=4 -> dst head j-4
__device__ int    g_deg[N_NODES];          // BSS-zeroed at load; re-zeroed by scanC each call
__device__ int    g_off[N_NODES + 1];      // CSR row offsets (by dst)
__device__ int    g_pos[N_NODES];          // scatter cursors
__device__ int    g_srcs[M_TOTAL];         // src ids grouped by dst
__device__ int    g_bsum[512];             // scan block sums

__device__ __forceinline__ float leaky(float e) { return e > 0.f ? e : 0.2f * e; }

__device__ __forceinline__ unsigned tf32(float f)
{
    unsigned u;
    asm("cvt.rna.tf32.f32 %0, %1;" : "=r"(u) : "f"(f));
    return u;
}

// ============================================================================
// K_gemm_tc: h = x @ W via mma.sync.m16n8k8.tf32, persistent strip loop.
// A-frags REGISTER DOUBLE-BUFFERED (prefetch k0+8 before consuming k0) to
// hide the cold-x global latency that bound R10 (L1 52%, tensor 17%).
// W staged once per block in smem stride-136 (conflict-free B-frag LDS).
// Fused: edge degree count (atomics, hidden under MMA) + u = W@att (block 0).
// h stored fp16. Exact-fp32 logits are computed later from x and u.
// ============================================================================
extern __shared__ float tc_smem[];  // Ws[128][136]
__global__ void __launch_bounds__(256, 2) k_gemm_tc(
    const float* __restrict__ x, const float* __restrict__ W,
    const float* __restrict__ att_src, const float* __restrict__ att_dst,
    const int* __restrict__ ei)
{
    float* Ws = tc_smem;
    const int t = threadIdx.x, warp = t >> 5, lane = t & 31;

    // fused degree count (edges only; self-loop folded into scanA as deg+1)
    for (int m = blockIdx.x * blockDim.x + t; m < N_EDGES; m += gridDim.x * blockDim.x)
        atomicAdd(&g_deg[ei[N_EDGES + m]], 1);

    // fused u = W @ att (block 0 only; consumed by k_logits two launches later)
    if (blockIdx.x == 0) {
        for (int e = t; e < HD * 8; e += 256) {
            int k = e >> 3, j = e & 7;
            int head = j & 3;
            const float* att = (j < 4) ? att_src : att_dst;
            float s = 0.f;
#pragma unroll
            for (int d = 0; d < 32; d++)
                s = fmaf(W[k * HD + head * 32 + d], att[head * 32 + d], s);
            g_u[k * 8 + j] = s;
        }
    }

    // stage W as tf32 bit patterns (once per block; read-only afterwards)
    for (int i = t; i < HD * HD; i += 256) {
        int k = i >> 7, c = i & 127;
        Ws[k * 136 + c] = __uint_as_float(tf32(W[i]));
    }
    __syncthreads();

    const int qa = lane & 3;
    const int kb_base = lane & 3;
    const int cb = lane >> 2;

    for (int strip = blockIdx.x; strip < NSTRIP; strip += gridDim.x) {
        const int ra = strip * 128 + warp * 16 + (lane >> 2);  // rows ra, ra+8
        const bool v0 = ra < N_NODES, v1 = (ra + 8) < N_NODES;
        const float* p0 = x + (long long)ra * HD + qa;
        const float* p1 = p0 + 8 * HD;

        float acc[16][4];
#pragma unroll
        for (int nt = 0; nt < 16; nt++)
#pragma unroll
            for (int q = 0; q < 4; q++) acc[nt][q] = 0.f;

        // prime k0 = 0
        unsigned ac0 = 0, ac1 = 0, ac2 = 0, ac3 = 0;
        if (v0) { ac0 = tf32(p0[0]); ac2 = tf32(p0[4]); }
        if (v1) { ac1 = tf32(p1[0]); ac3 = tf32(p1[4]); }

        for (int k0 = 0; k0 < HD; k0 += 8) {
            // prefetch next k-step BEFORE the MMA chain (double buffer)
            unsigned an0 = 0, an1 = 0, an2 = 0, an3 = 0;
            if (k0 + 8 < HD) {
                if (v0) { an0 = tf32(p0[k0 + 8]); an2 = tf32(p0[k0 + 12]); }
                if (v1) { an1 = tf32(p1[k0 + 8]); an3 = tf32(p1[k0 + 12]); }
            }
            const int kb = k0 + kb_base;
#pragma unroll
            for (int nt = 0; nt < 16; nt++) {
                unsigned b0 = __float_as_uint(Ws[kb * 136 + nt * 8 + cb]);
                unsigned b1 = __float_as_uint(Ws[(kb + 4) * 136 + nt * 8 + cb]);
                asm volatile(
                    "mma.sync.aligned.m16n8k8.row.col.f32.tf32.tf32.f32 "
                    "{%0,%1,%2,%3}, {%4,%5,%6,%7}, {%8,%9}, {%0,%1,%2,%3};"
                    : "+f"(acc[nt][0]), "+f"(acc[nt][1]), "+f"(acc[nt][2]), "+f"(acc[nt][3])
                    : "r"(ac0), "r"(ac1), "r"(ac2), "r"(ac3), "r"(b0), "r"(b1));
            }
            ac0 = an0; ac1 = an1; ac2 = an2; ac3 = an3;
        }

        // store h fp16: c0,c1 -> (ra, col..col+1); c2,c3 -> (ra+8, same cols)
#pragma unroll
        for (int nt = 0; nt < 16; nt++) {
            const int col = nt * 8 + 2 * qa;
            if (v0)
                *(__half2*)(g_h + (long long)ra * HD + col) =
                    __floats2half2_rn(acc[nt][0], acc[nt][1]);
            if (v1)
                *(__half2*)(g_h + (long long)(ra + 8) * HD + col) =
                    __floats2half2_rn(acc[nt][2], acc[nt][3]);
        }
    }
}

// ============================================================================
// CSR build: block scan -> (block-prefix + apply + deg rezero) -> scatter
// ============================================================================
__global__ void k_scanA()
{
    __shared__ int s[256];
    int t = threadIdx.x;
    int i = blockIdx.x * 256 + t;
    int v = (i < N_NODES) ? (g_deg[i] + 1) : 0;   // +1 = self loop
    s[t] = v;
    __syncthreads();
#pragma unroll
    for (int off = 1; off < 256; off <<= 1) {
        int u = (t >= off) ? s[t - off] : 0;
        __syncthreads();
        s[t] += u;
        __syncthreads();
    }
    if (i < N_NODES) g_off[i] = s[t] - v;       // exclusive within block
    if (t == 255) g_bsum[blockIdx.x] = s[255];  // block total
}

__global__ void k_scanC()  // global block-prefix + apply; rezero g_deg for next call
{
    __shared__ int pref;
    int t = threadIdx.x;
    if (t < 32) {
        int s = 0;
        for (int i = t; i < blockIdx.x; i += 32) s += g_bsum[i];
#pragma unroll
        for (int o = 16; o; o >>= 1) s += __shfl_xor_sync(0xffffffffu, s, o);
        if (t == 0) pref = s;
    }
    __syncthreads();
    int i = blockIdx.x * 256 + t;
    if (i < N_NODES) {
        int o = g_off[i] + pref;
        g_off[i] = o;
        g_pos[i] = o;
        g_deg[i] = 0;                            // ready for next kernel_launch call
    }
    if (i == 0) g_off[N_NODES] = M_TOTAL;
}

__global__ void k_scatter(const int* __restrict__ ei)   // launch idx 3 -> profiled
{
    int m = blockIdx.x * blockDim.x + threadIdx.x;
    if (m >= M_TOTAL) return;
    int src, dst;
    if (m < N_EDGES) { src = ei[m]; dst = ei[N_EDGES + m]; }
    else             { src = dst = m - N_EDGES; }
    int p = atomicAdd(&g_pos[dst], 1);
    g_srcs[p] = src;
}

// ============================================================================
// K_logits: a = x @ u  (exact fp32 logits; keeps the exp path off tf32).
// thread -> (node, j). Consecutive 8 threads share a row (coalesced/broadcast).
// ============================================================================
__global__ void k_logits(const float* __restrict__ x)
{
    int gid = blockIdx.x * blockDim.x + threadIdx.x;
    if (gid >= N_NODES * 8) return;
    int n = gid >> 3, j = gid & 7;
    const float4* xr = (const float4*)(x + (long long)n * HD);
    float s = 0.f;
#pragma unroll 8
    for (int k = 0; k < 32; k++) {
        float4 xv = __ldg(&xr[k]);
        s = fmaf(xv.x, __ldg(&g_u[(k * 4 + 0) * 8 + j]),
            fmaf(xv.y, __ldg(&g_u[(k * 4 + 1) * 8 + j]),
            fmaf(xv.z, __ldg(&g_u[(k * 4 + 2) * 8 + j]),
            fmaf(xv.w, __ldg(&g_u[(k * 4 + 3) * 8 + j]), s))));
    }
    if (j < 4) g_asrc[n * NHEAD + j] = s;
    else       g_adst[n * NHEAD + (j - 4)] = s;
}

// ============================================================================
// K_agg: one warp per dst node, TWO edges per iteration (half-warp per edge;
// lane = 16*half + q, q owns channels [8q, 8q+8) -> head q>>2; LDG.128 16B/lane).
// Halves loop trips, issue count, and exp count vs R6. Depth-1 prefetch kept.
// alpha = exp(leaky(.)) without max-shift (softmax shift-invariant; |logit|
// small). fp32 accumulate; cross-half shfl reduce; normalize+bias+ELU store.
// ============================================================================
__global__ void k_agg(const float* __restrict__ bias, float* __restrict__ out)
{
    int n = (blockIdx.x * blockDim.x + threadIdx.x) >> 5;
    int lane = threadIdx.x & 31;
    if (n >= N_NODES) return;
    const int half = lane >> 4;     // which edge of the pair
    const int q = lane & 15;        // channel group: channels 8q..8q+7
    const int head = q >> 2;
    const float adh = g_adst[n * NHEAD + head];

    const int row = g_off[n];
    const int end = g_off[n + 1];

    float acc[8];
#pragma unroll
    for (int p = 0; p < 8; p++) acc[p] = 0.f;
    float denom = 0.f;

    for (int base = row; base < end; base += 32) {
        const int cnt = min(32, end - base);
        int s_reg = (lane < cnt) ? g_srcs[base + lane] : 0;

        // prime pair 0: this half handles edge j = half
        bool val_c = half < cnt;
        int idx_c = val_c ? half : 0;
        int src_c = __shfl_sync(0xffffffffu, s_reg, idx_c);
        float as_c = __ldg(&g_asrc[src_c * NHEAD + head]);
        uint4 hu_c = *(const uint4*)(g_h + (long long)src_c * HD + q * 8);

        for (int j = 0; j < cnt; j += 2) {
            // prefetch next pair
            const int jn = j + 2 + half;
            const bool val_n = jn < cnt;
            float as_n = 0.f;
            uint4 hu_n = make_uint4(0, 0, 0, 0);
            if (j + 2 < cnt) {
                int idx_n = val_n ? jn : 0;
                int src_n = __shfl_sync(0xffffffffu, s_reg, idx_n);
                as_n = __ldg(&g_asrc[src_n * NHEAD + head]);
                hu_n = *(const uint4*)(g_h + (long long)src_n * HD + q * 8);
            }
            float ex = val_c ? __expf(leaky(as_c + adh)) : 0.f;
            denom += ex;
            const __half2* hp = (const __half2*)&hu_c;
#pragma unroll
            for (int p = 0; p < 4; p++) {
                float2 f = __half22float2(hp[p]);
                acc[2 * p]     = fmaf(ex, f.x, acc[2 * p]);
                acc[2 * p + 1] = fmaf(ex, f.y, acc[2 * p + 1]);
            }
            val_c = val_n; as_c = as_n; hu_c = hu_n;
        }
    }

    // cross-half reduction (both halves end with the full sums)
    denom += __shfl_xor_sync(0xffffffffu, denom, 16);
#pragma unroll
    for (int p = 0; p < 8; p++) acc[p] += __shfl_xor_sync(0xffffffffu, acc[p], 16);

    if (half == 0) {
        const float inv = 1.f / (denom + 1e-16f);
        float4 b0 = ((const float4*)bias)[q * 2];
        float4 b1 = ((const float4*)bias)[q * 2 + 1];
        float4 o0, o1;
        o0.x = acc[0] * inv + b0.x; o0.y = acc[1] * inv + b0.y;
        o0.z = acc[2] * inv + b0.z; o0.w = acc[3] * inv + b0.w;
        o1.x = acc[4] * inv + b1.x; o1.y = acc[5] * inv + b1.y;
        o1.z = acc[6] * inv + b1.z; o1.w = acc[7] * inv + b1.w;
        o0.x = o0.x > 0.f ? o0.x : expm1f(o0.x);
        o0.y = o0.y > 0.f ? o0.y : expm1f(o0.y);
        o0.z = o0.z > 0.f ? o0.z : expm1f(o0.z);
        o0.w = o0.w > 0.f ? o0.w : expm1f(o0.w);
        o1.x = o1.x > 0.f ? o1.x : expm1f(o1.x);
        o1.y = o1.y > 0.f ? o1.y : expm1f(o1.y);
        o1.z = o1.z > 0.f ? o1.z : expm1f(o1.z);
        o1.w = o1.w > 0.f ? o1.w : expm1f(o1.w);
        float4* op = (float4*)(out + (long long)n * HD + q * 8);
        op[0] = o0;
        op[1] = o1;
    }
}

// ============================================================================
extern "C" void kernel_launch(void* const* d_in, const int* in_sizes, int n_in,
                              void* d_out, int out_size)
{
    const float* x    = (const float*)d_in[0];
    const int*   ei   = (const int*)d_in[1];     // int32 (JAX x64 disabled)
    const float* W    = (const float*)d_in[2];
    const float* aS   = (const float*)d_in[3];
    const float* aD   = (const float*)d_in[4];
    const float* bias = (const float*)d_in[5];
    float*       out  = (float*)d_out;

    const int tc_smem_bytes = 128 * 136 * (int)sizeof(float);  // 69632 B
    cudaFuncSetAttribute(k_gemm_tc, cudaFuncAttributeMaxDynamicSharedMemorySize,
                         tc_smem_bytes);

    k_gemm_tc<<<296, 256, tc_smem_bytes>>>(x, W, aS, aD, ei);  // idx 0 (fused count + u)
    k_scanA<<<NB, 256>>>();                                    // idx 1
    k_scanC<<<NB, 256>>>();                                    // idx 2
    k_scatter<<<(M_TOTAL + 255) / 256, 256>>>(ei);             // idx 3 (profiled)
    k_logits<<<(N_NODES * 8 + 255) / 256, 256>>>(x);           // idx 4
    k_agg<<<(N_NODES * 32 + 255) / 256, 256>>>(bias, out);     // idx 5
}